// round 1
// baseline (speedup 1.0000x reference)
#include <cuda_runtime.h>

#define NMAX 100000
#define EMAX 3200000
#define HD 32
#define POOL_BLOCKS 128

// ---------------- scratch (static __device__, no allocation) ----------------
__device__ float  d_T[NMAX * HD];        // per-node transformed features [V,h]@W_top
__device__ float  d_h[NMAX * HD];        // relu(agg)
__device__ float2 d_V[NMAX];             // running V
__device__ uint2  d_csr[EMAX];           // (sender, mask bits), CSR order by receiver
__device__ int    d_eid[EMAX];           // original edge id, CSR order
__device__ int    d_rowptr[NMAX + 1];
__device__ int    d_cursor[NMAX];        // counts, then running cursor
__device__ float4 d_S4[NMAX];            // sum(mask*ef) per receiver
__device__ float  d_Smask[NMAX];         // sum(mask) per receiver
__device__ float  d_partial[POOL_BLOCKS * HD];
__device__ float  d_g[HD];               // global supernode state
__device__ float  d_c[HD];               // g@W_n_bottom + b_n (per layer)

// ---------------- CSR build ----------------
__global__ void k_zero(int N) {
    int i = blockIdx.x * blockDim.x + threadIdx.x;
    if (i < N) d_cursor[i] = 0;
    if (i < HD) d_g[i] = 0.f;
}

__global__ void k_count(const int* __restrict__ recv, int E) {
    int e = blockIdx.x * blockDim.x + threadIdx.x;
    if (e < E) atomicAdd(&d_cursor[recv[e]], 1);
}

__global__ void k_scan(int N) {
    __shared__ int sh[1024];
    int t = threadIdx.x;
    int chunk = (N + 1023) >> 10;
    int beg = t * chunk;
    int end = min(beg + chunk, N);
    int s = 0;
    for (int i = beg; i < end; i++) s += d_cursor[i];
    sh[t] = s;
    __syncthreads();
    // Hillis-Steele inclusive scan over 1024 partials
    for (int off = 1; off < 1024; off <<= 1) {
        int v = (t >= off) ? sh[t - off] : 0;
        __syncthreads();
        sh[t] += v;
        __syncthreads();
    }
    int run = (t == 0) ? 0 : sh[t - 1];  // exclusive prefix of this chunk
    for (int i = beg; i < end; i++) {
        int c = d_cursor[i];
        d_rowptr[i] = run;
        d_cursor[i] = run;  // becomes fill cursor
        run += c;
    }
    if (t == 1023) d_rowptr[N] = sh[1023];
}

__global__ void k_fill(const int* __restrict__ send, const int* __restrict__ recv,
                       const float* __restrict__ mask, int E) {
    int e = blockIdx.x * blockDim.x + threadIdx.x;
    if (e < E) {
        int r = recv[e];
        int pos = atomicAdd(&d_cursor[r], 1);
        d_csr[pos] = make_uint2((unsigned)send[e], __float_as_uint(mask[e]));
        d_eid[pos] = e;
    }
}

// per-receiver layer-independent edge-feature sums
__global__ void k_s5(const float4* __restrict__ ef, int N) {
    int warp = (blockIdx.x * blockDim.x + threadIdx.x) >> 5;
    int lane = threadIdx.x & 31;
    if (warp >= N) return;
    int start = d_rowptr[warp], end = d_rowptr[warp + 1];
    float ax = 0.f, ay = 0.f, az = 0.f, aw = 0.f, am = 0.f;
    for (int p = start + lane; p < end; p += 32) {
        float m = __uint_as_float(d_csr[p].y);
        float4 f = ef[d_eid[p]];
        ax += m * f.x; ay += m * f.y; az += m * f.z; aw += m * f.w; am += m;
    }
    #pragma unroll
    for (int o = 16; o; o >>= 1) {
        ax += __shfl_xor_sync(~0u, ax, o);
        ay += __shfl_xor_sync(~0u, ay, o);
        az += __shfl_xor_sync(~0u, az, o);
        aw += __shfl_xor_sync(~0u, aw, o);
        am += __shfl_xor_sync(~0u, am, o);
    }
    if (lane == 0) {
        d_S4[warp] = make_float4(ax, ay, az, aw);
        d_Smask[warp] = am;
    }
}

// ---------------- layer pipeline ----------------
// init: h0 = PQ@W_in + b_in ; V0=(1,0) ; T0 = [V0,h0] @ W_msg[0][0:34]
__global__ void k_init(const float2* __restrict__ PQ,
                       const float* __restrict__ W_in, const float* __restrict__ b_in,
                       const float* __restrict__ W_msg, int N) {
    __shared__ float sWin[2 * HD], sb[HD], sWt[34 * HD];
    for (int i = threadIdx.x; i < 2 * HD; i += blockDim.x) sWin[i] = W_in[i];
    for (int i = threadIdx.x; i < HD; i += blockDim.x) sb[i] = b_in[i];
    for (int i = threadIdx.x; i < 34 * HD; i += blockDim.x) sWt[i] = W_msg[i];
    __syncthreads();
    int warp = (blockIdx.x * blockDim.x + threadIdx.x) >> 5;
    int lane = threadIdx.x & 31;
    if (warp >= N) return;
    float2 pq = PQ[warp];
    float h = pq.x * sWin[lane] + pq.y * sWin[HD + lane] + sb[lane];
    if (lane == 0) d_V[warp] = make_float2(1.f, 0.f);
    float t = sWt[lane];  // V0=1 * W_top[0][lane], V1=0
    #pragma unroll
    for (int k = 0; k < HD; k++)
        t += __shfl_sync(~0u, h, k) * sWt[(2 + k) * HD + lane];
    d_T[warp * HD + lane] = t;
}

// aggregation: warp per receiver, lane per hidden dim
__global__ void k_agg(const float* __restrict__ W_msg, const float* __restrict__ b_msg,
                      int l, int N) {
    __shared__ float sWb[4 * HD], sb[HD];
    const float* Wl = W_msg + l * 38 * HD;
    for (int i = threadIdx.x; i < 4 * HD; i += blockDim.x) sWb[i] = Wl[34 * HD + i];
    for (int i = threadIdx.x; i < HD; i += blockDim.x) sb[i] = b_msg[l * HD + i];
    __syncthreads();
    int warp = (blockIdx.x * blockDim.x + threadIdx.x) >> 5;
    int lane = threadIdx.x & 31;
    if (warp >= N) return;
    float4 s4 = d_S4[warp];
    float sm = d_Smask[warp];
    float acc0 = s4.x * sWb[lane] + s4.y * sWb[HD + lane] +
                 s4.z * sWb[2 * HD + lane] + s4.w * sWb[3 * HD + lane] + sm * sb[lane];
    float acc1 = 0.f, acc2 = 0.f, acc3 = 0.f;
    int p = d_rowptr[warp], end = d_rowptr[warp + 1];
    for (; p + 4 <= end; p += 4) {
        uint2 e0 = d_csr[p], e1 = d_csr[p + 1], e2 = d_csr[p + 2], e3 = d_csr[p + 3];
        acc0 += __uint_as_float(e0.y) * d_T[e0.x * HD + lane];
        acc1 += __uint_as_float(e1.y) * d_T[e1.x * HD + lane];
        acc2 += __uint_as_float(e2.y) * d_T[e2.x * HD + lane];
        acc3 += __uint_as_float(e3.y) * d_T[e3.x * HD + lane];
    }
    for (; p < end; p++) {
        uint2 e0 = d_csr[p];
        acc0 += __uint_as_float(e0.y) * d_T[e0.x * HD + lane];
    }
    d_h[warp * HD + lane] = fmaxf(acc0 + acc1 + acc2 + acc3, 0.f);
}

// deterministic two-stage mean pooling
__global__ void k_pool(int N) {
    int t = threadIdx.x, j = t & 31, g = t >> 5;
    __shared__ float sh[8][HD];
    float s = 0.f;
    for (int r = blockIdx.x * 8 + g; r < N; r += POOL_BLOCKS * 8)
        s += d_h[r * HD + j];
    sh[g][j] = s;
    __syncthreads();
    if (g == 0) {
        float v = 0.f;
        #pragma unroll
        for (int q = 0; q < 8; q++) v += sh[q][j];
        d_partial[blockIdx.x * HD + j] = v;
    }
}

// global supernode update + precompute c = g_new @ W_n[32:64] + b_n
__global__ void k_g(const float* __restrict__ W_g, const float* __restrict__ b_g,
                    const float* __restrict__ W_n, const float* __restrict__ b_n,
                    int l, int N) {
    int j = threadIdx.x;  // 32 threads
    float p = 0.f;
    #pragma unroll 8
    for (int b = 0; b < POOL_BLOCKS; b++) p += d_partial[b * HD + j];
    p /= (float)N;
    float gold = d_g[j];
    const float* Wg = W_g + l * 64 * HD;
    float acc = b_g[l * HD + j];
    #pragma unroll
    for (int k = 0; k < HD; k++) {
        acc += __shfl_sync(~0u, gold, k) * Wg[k * HD + j];
        acc += __shfl_sync(~0u, p, k) * Wg[(HD + k) * HD + j];
    }
    float gn = fmaxf(acc, 0.f);
    d_g[j] = gn;
    const float* Wn = W_n + l * 64 * HD;
    float c = b_n[l * HD + j];
    #pragma unroll
    for (int k = 0; k < HD; k++)
        c += __shfl_sync(~0u, gn, k) * Wn[(HD + k) * HD + j];
    d_c[j] = c;
}

// node update: h' = relu(h@Wn_top + c); V += h'@W_out + b_out; T_next = [V,h']@W_top(l+1)
__global__ void k_node(const float* __restrict__ W_n, const float* __restrict__ W_out,
                       const float* __restrict__ b_out, const float* __restrict__ W_msg,
                       int l, int N, int last, float2* __restrict__ outV) {
    __shared__ float sWn[HD * HD], sWo[HD * 2], sWt[34 * HD], sc[HD];
    const float* Wn = W_n + l * 64 * HD;
    for (int i = threadIdx.x; i < HD * HD; i += blockDim.x) sWn[i] = Wn[i];
    for (int i = threadIdx.x; i < HD * 2; i += blockDim.x) sWo[i] = W_out[l * HD * 2 + i];
    if (!last) {
        const float* Wt = W_msg + (l + 1) * 38 * HD;
        for (int i = threadIdx.x; i < 34 * HD; i += blockDim.x) sWt[i] = Wt[i];
    }
    for (int i = threadIdx.x; i < HD; i += blockDim.x) sc[i] = d_c[i];
    __syncthreads();
    int warp = (blockIdx.x * blockDim.x + threadIdx.x) >> 5;
    int lane = threadIdx.x & 31;
    if (warp >= N) return;
    float x = d_h[warp * HD + lane];
    float acc = sc[lane];
    #pragma unroll
    for (int k = 0; k < HD; k++)
        acc += __shfl_sync(~0u, x, k) * sWn[k * HD + lane];
    float hn = fmaxf(acc, 0.f);
    float v0 = hn * sWo[lane * 2 + 0];
    float v1 = hn * sWo[lane * 2 + 1];
    #pragma unroll
    for (int o = 16; o; o >>= 1) {
        v0 += __shfl_xor_sync(~0u, v0, o);
        v1 += __shfl_xor_sync(~0u, v1, o);
    }
    float2 v = d_V[warp];
    v.x += v0 + b_out[l * 2 + 0];
    v.y += v1 + b_out[l * 2 + 1];
    if (last) {
        if (lane == 0) outV[warp] = v;
    } else {
        if (lane == 0) d_V[warp] = v;
        float t = v.x * sWt[lane] + v.y * sWt[HD + lane];
        #pragma unroll
        for (int k = 0; k < HD; k++)
            t += __shfl_sync(~0u, hn, k) * sWt[(2 + k) * HD + lane];
        d_T[warp * HD + lane] = t;
    }
}

// ---------------- launch ----------------
extern "C" void kernel_launch(void* const* d_in, const int* in_sizes, int n_in,
                              void* d_out, int out_size) {
    const float2* PQ    = (const float2*)d_in[0];
    const int*    send  = (const int*)d_in[1];
    const int*    recv  = (const int*)d_in[2];
    const float4* ef    = (const float4*)d_in[3];
    const float*  mask  = (const float*)d_in[4];
    const float*  W_in  = (const float*)d_in[5];
    const float*  b_in  = (const float*)d_in[6];
    const float*  W_msg = (const float*)d_in[7];
    const float*  b_msg = (const float*)d_in[8];
    const float*  W_g   = (const float*)d_in[9];
    const float*  b_g   = (const float*)d_in[10];
    const float*  W_n   = (const float*)d_in[11];
    const float*  b_n   = (const float*)d_in[12];
    const float*  W_out = (const float*)d_in[13];
    const float*  b_out = (const float*)d_in[14];

    int N = in_sizes[0] / 2;
    int E = in_sizes[1];
    int nwb = (N + 7) / 8;        // warp-per-node blocks of 256 threads
    int eb  = (E + 255) / 256;

    k_zero<<<(N + 255) / 256, 256>>>(N);
    k_count<<<eb, 256>>>(recv, E);
    k_scan<<<1, 1024>>>(N);
    k_fill<<<eb, 256>>>(send, recv, mask, E);
    k_s5<<<nwb, 256>>>(ef, N);
    k_init<<<nwb, 256>>>(PQ, W_in, b_in, W_msg, N);

    for (int l = 0; l < 3; l++) {
        k_agg<<<nwb, 256>>>(W_msg, b_msg, l, N);
        k_pool<<<POOL_BLOCKS, 256>>>(N);
        k_g<<<1, 32>>>(W_g, b_g, W_n, b_n, l, N);
        k_node<<<nwb, 256>>>(W_n, W_out, b_out, W_msg, l, N, l == 2, (float2*)d_out);
    }
}

// round 3
// speedup vs baseline: 1.7591x; 1.7591x over previous
#include <cuda_runtime.h>

#define NMAX 100000
#define EMAX 3200000
#define HD 32

// ---------------- scratch (static __device__, no allocation) ----------------
__device__ __align__(16) float  d_T[NMAX * HD];   // per-node transformed feats [V,h]@W_top
__device__ __align__(16) float  d_u[NMAX * HD];   // h @ W_n_top (pre-relu node update)
__device__ float2 d_V[NMAX];                      // running V
__device__ __align__(16) uint2  d_csr[EMAX];      // (sender, mask bits), CSR order
__device__ __align__(16) float4 d_efm[EMAX];      // mask*edge_features, CSR order
__device__ __align__(16) int    d_rowptr[NMAX + 8];
__device__ __align__(16) int    d_cursor[NMAX + 8];
__device__ float4 d_S4[NMAX];                     // sum(mask*ef) per receiver
__device__ float  d_Smask[NMAX];                  // sum(mask) per receiver
__device__ float  d_pool[HD];                     // atomic pooled sum of h
__device__ float  d_g[HD];                        // global supernode state
__device__ float  d_c[HD];                        // g@W_n_bot + b_n (per layer)

// ---------------- CSR build ----------------
__global__ void k_zero(int N) {
    int i = blockIdx.x * blockDim.x + threadIdx.x;
    if (i < N) d_cursor[i] = 0;
    if (i < HD) { d_g[i] = 0.f; d_pool[i] = 0.f; }
}

__global__ void k_count(const int* __restrict__ recv, int E) {
    int base = (blockIdx.x * blockDim.x + threadIdx.x) * 4;
    if (base + 4 <= E) {
        int4 r = *(const int4*)(recv + base);
        atomicAdd(&d_cursor[r.x], 1);
        atomicAdd(&d_cursor[r.y], 1);
        atomicAdd(&d_cursor[r.z], 1);
        atomicAdd(&d_cursor[r.w], 1);
    } else {
        for (int e = base; e < E; e++) atomicAdd(&d_cursor[recv[e]], 1);
    }
}

__global__ void k_scan(int N) {
    __shared__ int sh[1024];
    const int CH = 100;                 // 1024*100 >= 100000, beg 4-aligned
    int t = threadIdx.x;
    int beg = t * CH;
    int end = min(beg + CH, N);
    int s = 0;
    if (beg < N) {
        int i = beg;
        for (; i + 4 <= end; i += 4) {
            int4 v = *(const int4*)&d_cursor[i];
            s += v.x + v.y + v.z + v.w;
        }
        for (; i < end; i++) s += d_cursor[i];
    }
    sh[t] = s;
    __syncthreads();
    for (int off = 1; off < 1024; off <<= 1) {
        int v = (t >= off) ? sh[t - off] : 0;
        __syncthreads();
        sh[t] += v;
        __syncthreads();
    }
    int run = (t == 0) ? 0 : sh[t - 1];
    if (beg < N) {
        int i = beg;
        for (; i + 4 <= end; i += 4) {
            int4 v = *(const int4*)&d_cursor[i];
            int4 r;
            r.x = run; run += v.x;
            r.y = run; run += v.y;
            r.z = run; run += v.z;
            r.w = run; run += v.w;
            *(int4*)&d_rowptr[i] = r;
            *(int4*)&d_cursor[i] = r;
        }
        for (; i < end; i++) {
            int c = d_cursor[i];
            d_rowptr[i] = run; d_cursor[i] = run; run += c;
        }
    }
    if (t == 1023) d_rowptr[N] = sh[1023];
}

__global__ void k_fill(const int* __restrict__ send, const int* __restrict__ recv,
                       const float* __restrict__ mask, const float4* __restrict__ ef,
                       int E) {
    int e = blockIdx.x * blockDim.x + threadIdx.x;
    if (e < E) {
        int r = recv[e];
        int pos = atomicAdd(&d_cursor[r], 1);
        float m = mask[e];
        d_csr[pos] = make_uint2((unsigned)send[e], __float_as_uint(m));
        float4 f = ef[e];
        d_efm[pos] = make_float4(m * f.x, m * f.y, m * f.z, m * f.w);
    }
}

// per-receiver layer-independent edge-feature sums (fully sequential reads)
__global__ void k_s5(int N) {
    int warp = (blockIdx.x * blockDim.x + threadIdx.x) >> 5;
    int lane = threadIdx.x & 31;
    if (warp >= N) return;
    int start = d_rowptr[warp], end = d_rowptr[warp + 1];
    float ax = 0.f, ay = 0.f, az = 0.f, aw = 0.f, am = 0.f;
    for (int p = start + lane; p < end; p += 32) {
        am += __uint_as_float(d_csr[p].y);
        float4 f = d_efm[p];
        ax += f.x; ay += f.y; az += f.z; aw += f.w;
    }
    #pragma unroll
    for (int o = 16; o; o >>= 1) {
        ax += __shfl_xor_sync(~0u, ax, o);
        ay += __shfl_xor_sync(~0u, ay, o);
        az += __shfl_xor_sync(~0u, az, o);
        aw += __shfl_xor_sync(~0u, aw, o);
        am += __shfl_xor_sync(~0u, am, o);
    }
    if (lane == 0) {
        d_S4[warp] = make_float4(ax, ay, az, aw);
        d_Smask[warp] = am;
    }
}

// ---------------- layer pipeline ----------------
// init: h0 = PQ@W_in + b_in ; V0=(1,0) ; T0 = [V0,h0] @ W_msg[0][0:34]
__global__ void k_init(const float2* __restrict__ PQ,
                       const float* __restrict__ W_in, const float* __restrict__ b_in,
                       const float* __restrict__ W_msg, int N) {
    __shared__ float sWin[2 * HD], sb[HD], sWt[34 * HD];
    for (int i = threadIdx.x; i < 2 * HD; i += blockDim.x) sWin[i] = W_in[i];
    for (int i = threadIdx.x; i < HD; i += blockDim.x) sb[i] = b_in[i];
    for (int i = threadIdx.x; i < 34 * HD; i += blockDim.x) sWt[i] = W_msg[i];
    __syncthreads();
    int warp = (blockIdx.x * blockDim.x + threadIdx.x) >> 5;
    int lane = threadIdx.x & 31;
    if (warp >= N) return;
    float2 pq = PQ[warp];
    float h = pq.x * sWin[lane] + pq.y * sWin[HD + lane] + sb[lane];
    if (lane == 0) d_V[warp] = make_float2(1.f, 0.f);
    float t = sWt[lane];  // V0=(1,0): 1*W_top[0][lane]
    #pragma unroll
    for (int k = 0; k < HD; k++)
        t += __shfl_sync(~0u, h, k) * sWt[(2 + k) * HD + lane];
    d_T[warp * HD + lane] = t;
}

// aggregation: warp per receiver; fused pool accumulation + u = h@Wn_top
__global__ void __launch_bounds__(256) k_agg(
        const float* __restrict__ W_msg, const float* __restrict__ b_msg,
        const float* __restrict__ W_n, int l, int N) {
    __shared__ float sWb[4 * HD], sb[HD], sWn[HD * HD];
    __shared__ float shp[8][HD];
    const float* Wl = W_msg + l * 38 * HD;
    const float* Wn = W_n + l * 64 * HD;
    for (int i = threadIdx.x; i < 4 * HD; i += blockDim.x) sWb[i] = Wl[34 * HD + i];
    for (int i = threadIdx.x; i < HD; i += blockDim.x) sb[i] = b_msg[l * HD + i];
    for (int i = threadIdx.x; i < HD * HD; i += blockDim.x) sWn[i] = Wn[i];
    __syncthreads();
    int warp = (blockIdx.x * blockDim.x + threadIdx.x) >> 5;
    int w = threadIdx.x >> 5;
    int lane = threadIdx.x & 31;
    float h = 0.f;
    if (warp < N) {
        float4 s4 = d_S4[warp];
        float sm = d_Smask[warp];
        float acc0 = s4.x * sWb[lane] + s4.y * sWb[HD + lane] +
                     s4.z * sWb[2 * HD + lane] + s4.w * sWb[3 * HD + lane] + sm * sb[lane];
        float acc1 = 0.f, acc2 = 0.f, acc3 = 0.f;
        int p = d_rowptr[warp], end = d_rowptr[warp + 1];
        if ((p & 1) && p < end) {  // align to uint4
            uint2 e = d_csr[p];
            acc1 += __uint_as_float(e.y) * d_T[e.x * HD + lane];
            p++;
        }
        for (; p + 4 <= end; p += 4) {
            uint4 a = *(const uint4*)&d_csr[p];
            uint4 b = *(const uint4*)&d_csr[p + 2];
            acc0 += __uint_as_float(a.y) * d_T[a.x * HD + lane];
            acc1 += __uint_as_float(a.w) * d_T[a.z * HD + lane];
            acc2 += __uint_as_float(b.y) * d_T[b.x * HD + lane];
            acc3 += __uint_as_float(b.w) * d_T[b.z * HD + lane];
        }
        if (p + 2 <= end) {
            uint4 a = *(const uint4*)&d_csr[p];
            acc0 += __uint_as_float(a.y) * d_T[a.x * HD + lane];
            acc1 += __uint_as_float(a.w) * d_T[a.z * HD + lane];
            p += 2;
        }
        if (p < end) {
            uint2 e = d_csr[p];
            acc2 += __uint_as_float(e.y) * d_T[e.x * HD + lane];
        }
        h = fmaxf(acc0 + acc1 + acc2 + acc3, 0.f);
    }
    shp[w][lane] = h;
    __syncthreads();
    if (w == 0) {
        float ps = 0.f;
        #pragma unroll
        for (int q = 0; q < 8; q++) ps += shp[q][lane];
        atomicAdd(&d_pool[lane], ps);
    }
    if (warp < N) {
        float u = 0.f;
        #pragma unroll
        for (int k = 0; k < HD; k++)
            u += __shfl_sync(~0u, h, k) * sWn[k * HD + lane];
        d_u[warp * HD + lane] = u;
    }
}

// global supernode update + precompute c = g_new @ W_n[32:64] + b_n ; re-zero pool
__global__ void k_g(const float* __restrict__ W_g, const float* __restrict__ b_g,
                    const float* __restrict__ W_n, const float* __restrict__ b_n,
                    int l, int N) {
    int j = threadIdx.x;  // 32 threads
    float p = d_pool[j] / (float)N;
    d_pool[j] = 0.f;
    float gold = d_g[j];
    const float* Wg = W_g + l * 64 * HD;
    float acc = b_g[l * HD + j];
    #pragma unroll
    for (int k = 0; k < HD; k++) {
        acc += __shfl_sync(~0u, gold, k) * Wg[k * HD + j];
        acc += __shfl_sync(~0u, p, k) * Wg[(HD + k) * HD + j];
    }
    float gn = fmaxf(acc, 0.f);
    d_g[j] = gn;
    const float* Wn = W_n + l * 64 * HD;
    float c = b_n[l * HD + j];
    #pragma unroll
    for (int k = 0; k < HD; k++)
        c += __shfl_sync(~0u, gn, k) * Wn[(HD + k) * HD + j];
    d_c[j] = c;
}

// node update: hn = relu(u + c); V += hn@W_out + b_out; T_next = [V,hn]@W_top(l+1)
__global__ void k_node(const float* __restrict__ W_out, const float* __restrict__ b_out,
                       const float* __restrict__ W_msg,
                       int l, int N, int last, float2* __restrict__ outV) {
    __shared__ float sWo[HD * 2], sWt[34 * HD], sc[HD];
    for (int i = threadIdx.x; i < HD * 2; i += blockDim.x) sWo[i] = W_out[l * HD * 2 + i];
    if (!last) {
        const float* Wt = W_msg + (l + 1) * 38 * HD;
        for (int i = threadIdx.x; i < 34 * HD; i += blockDim.x) sWt[i] = Wt[i];
    }
    for (int i = threadIdx.x; i < HD; i += blockDim.x) sc[i] = d_c[i];
    __syncthreads();
    int warp = (blockIdx.x * blockDim.x + threadIdx.x) >> 5;
    int lane = threadIdx.x & 31;
    if (warp >= N) return;
    float hn = fmaxf(d_u[warp * HD + lane] + sc[lane], 0.f);
    float v0 = hn * sWo[lane * 2 + 0];
    float v1 = hn * sWo[lane * 2 + 1];
    #pragma unroll
    for (int o = 16; o; o >>= 1) {
        v0 += __shfl_xor_sync(~0u, v0, o);
        v1 += __shfl_xor_sync(~0u, v1, o);
    }
    float2 v = d_V[warp];
    v.x += v0 + b_out[l * 2 + 0];
    v.y += v1 + b_out[l * 2 + 1];
    if (last) {
        if (lane == 0) outV[warp] = v;
    } else {
        if (lane == 0) d_V[warp] = v;
        float t = v.x * sWt[lane] + v.y * sWt[HD + lane];
        #pragma unroll
        for (int k = 0; k < HD; k++)
            t += __shfl_sync(~0u, hn, k) * sWt[(2 + k) * HD + lane];
        d_T[warp * HD + lane] = t;
    }
}

// ---------------- launch ----------------
extern "C" void kernel_launch(void* const* d_in, const int* in_sizes, int n_in,
                              void* d_out, int out_size) {
    const float2* PQ    = (const float2*)d_in[0];
    const int*    send  = (const int*)d_in[1];
    const int*    recv  = (const int*)d_in[2];
    const float4* ef    = (const float4*)d_in[3];
    const float*  mask  = (const float*)d_in[4];
    const float*  W_in  = (const float*)d_in[5];
    const float*  b_in  = (const float*)d_in[6];
    const float*  W_msg = (const float*)d_in[7];
    const float*  b_msg = (const float*)d_in[8];
    const float*  W_g   = (const float*)d_in[9];
    const float*  b_g   = (const float*)d_in[10];
    const float*  W_n   = (const float*)d_in[11];
    const float*  b_n   = (const float*)d_in[12];
    const float*  W_out = (const float*)d_in[13];
    const float*  b_out = (const float*)d_in[14];

    int N = in_sizes[0] / 2;
    int E = in_sizes[1];
    int nwb = (N + 7) / 8;          // warp-per-node, 256-thread blocks
    int eb  = (E + 255) / 256;
    int eb4 = (E + 1023) / 1024;

    k_zero<<<(N + 255) / 256, 256>>>(N);
    k_count<<<eb4, 256>>>(recv, E);
    k_scan<<<1, 1024>>>(N);
    k_fill<<<eb, 256>>>(send, recv, mask, ef, E);
    k_s5<<<nwb, 256>>>(N);
    k_init<<<nwb, 256>>>(PQ, W_in, b_in, W_msg, N);

    for (int l = 0; l < 3; l++) {
        k_agg<<<nwb, 256>>>(W_msg, b_msg, W_n, l, N);
        k_g<<<1, 32>>>(W_g, b_g, W_n, b_n, l, N);
        k_node<<<nwb, 256>>>(W_out, b_out, W_msg, l, N, l == 2, (float2*)d_out);
    }
}